// round 5
// baseline (speedup 1.0000x reference)
#include <cuda_runtime.h>
#include <cstdint>

#define Nn 1024
#define Hh 100
#define Gg 400
#define KE 125
#define Ll 40
#define EPSV 1e-20f
#define RING 4

// ---------------- scratch (device globals; no allocation allowed) ----------------
__device__ float g_E[Nn * KE];   // embeddings [1024,125]
__device__ float g_P[Nn * Gg];   // layer0 input projection (gemm output)
__device__ float g_H1[Nn * Hh];  // layer1 hidden states
__device__ float g_u[2 * Hh + 1];
__device__ float g_EA[Nn];
__device__ float g_EB[Nn];
__device__ float g_S;

// ---------------- helpers ----------------
__device__ __forceinline__ float tanhap(float x) {
    float r;
    asm("tanh.approx.f32 %0, %1;" : "=f"(r) : "f"(x));
    return r;
}
#define FMA2(acc, a, b) asm("fma.rn.f32x2 %0, %1, %2, %0;" : "+l"(acc) : "l"(a), "l"(b))
__device__ __forceinline__ float unpack_sum(unsigned long long v) {
    float lo, hi;
    asm("mov.b64 {%0, %1}, %2;" : "=f"(lo), "=f"(hi) : "l"(v));
    return lo + hi;
}
__device__ __forceinline__ uint32_t smem_u32(const void* p) {
    return (uint32_t)__cvta_generic_to_shared(p);
}
__device__ __forceinline__ uint32_t mapa_u32(uint32_t a, uint32_t rank) {
    uint32_t r;
    asm("mapa.shared::cluster.u32 %0, %1, %2;" : "=r"(r) : "r"(a), "r"(rank));
    return r;
}
__device__ __forceinline__ void mbar_init1(uint32_t a) {
    asm volatile("mbarrier.init.shared.b64 [%0], 1;" :: "r"(a) : "memory");
}
__device__ __forceinline__ void mbar_arrive_remote(uint32_t ra) {
    asm volatile("mbarrier.arrive.release.cluster.shared::cluster.b64 _, [%0];"
                 :: "r"(ra) : "memory");
}
__device__ __forceinline__ void mbar_wait(uint32_t a, uint32_t par) {
    asm volatile(
        "{\n\t.reg .pred P;\n"
        "W_%=:\n\t"
        "mbarrier.try_wait.parity.acquire.cluster.shared::cta.b64 P, [%0], %1, 0x989680;\n\t"
        "@P bra D_%=;\n\t"
        "bra W_%=;\n"
        "D_%=:\n\t}"
        :: "r"(a), "r"(par) : "memory");
}
__device__ __forceinline__ void st_remote(uint32_t ra, float v) {
    asm volatile("st.shared::cluster.b32 [%0], %1;" :: "r"(ra), "r"(__float_as_uint(v)) : "memory");
}
__device__ __forceinline__ void cluster_sync_all() {
    asm volatile("barrier.cluster.arrive.aligned;" ::: "memory");
    asm volatile("barrier.cluster.wait.aligned;" ::: "memory");
}

// ---------------- K0: embedding gather ----------------
__global__ void gather_emb(const int* __restrict__ wi, const int* __restrict__ ti,
                           const float* __restrict__ wt, const float* __restrict__ tt) {
    int t = blockIdx.x;
    int w = wi[t];
    int g = ti[t];
    for (int j = threadIdx.x; j < KE; j += blockDim.x)
        g_E[t * KE + j] = (j < 100) ? wt[w * 100 + j] : tt[g * 25 + (j - 100)];
}

// ---------------- K1: P0[1024,400] = E @ Wih0^T + b_ih0 + b_hh0 ----------------
__global__ __launch_bounds__(256) void gemm_bias(const float* __restrict__ X,
                                                 const float* __restrict__ W,
                                                 const float* __restrict__ b1,
                                                 const float* __restrict__ b2,
                                                 float* __restrict__ C, int K) {
    __shared__ float Xs[64 * 127];
    __shared__ float Ws[32 * 127];
    int m0 = blockIdx.y * 64;
    int n0 = blockIdx.x * 32;
    int tid = threadIdx.x;

    for (int idx = tid; idx < 64 * K; idx += 256) {
        int r = idx / K, c = idx - r * K;
        Xs[r * 127 + c] = X[(m0 + r) * K + c];
    }
    for (int idx = tid; idx < 32 * K; idx += 256) {
        int r = idx / K, c = idx - r * K;
        int n = n0 + r;
        Ws[r * 127 + c] = (n < Gg) ? W[n * K + c] : 0.f;
    }
    __syncthreads();

    int ty = tid >> 5, tx = tid & 31;
    float acc[8] = {0, 0, 0, 0, 0, 0, 0, 0};
    for (int k = 0; k < K; k++) {
        float wv = Ws[tx * 127 + k];
#pragma unroll
        for (int r = 0; r < 8; r++)
            acc[r] = fmaf(Xs[(ty + 8 * r) * 127 + k], wv, acc[r]);
    }
    int n = n0 + tx;
    if (n < Gg) {
        float bb = b1[n] + b2[n];
#pragma unroll
        for (int r = 0; r < 8; r++)
            C[(m0 + ty + 8 * r) * Gg + n] = acc[r] + bb;
    }
}

// ---------------- K2: 3-stage cluster LSTM pipeline (DSMEM + mbarrier handoff) ----------------
// cluster (3,1,1): rank0=A layer0 recurrence, rank1=B layer1 input projection,
// rank2=C layer1 recurrence. A->B h rows and B->C P1 rows go via st.shared::cluster
// into 4-deep smem rings; signaling via cluster mbarriers (posted arrives, no
// gpu-scope fence on the critical path -- the R4 killer). Comm warp (tid>=800)
// waits one step ahead. 832 thr -> reg cap 78; compute thread ~72 regs (R4-measured).
__global__ __launch_bounds__(832, 1) __cluster_dims__(3, 1, 1)
void lstm_pipe(const float* __restrict__ Whh0,
               const float* __restrict__ Wih1,
               const float* __restrict__ Whh1,
               const float* __restrict__ bih1,
               const float* __restrict__ bhh1) {
    __shared__ __align__(16) float h_sh[Hh];           // A/C: own hidden state
    __shared__ __align__(16) float hring[RING][Hh];    // B: h0 ring (written remotely by A)
    __shared__ __align__(16) float pring[RING][Gg];    // C: P1 ring (written remotely by B)
    __shared__ __align__(16) float pbuf[2][Gg];        // A: P0 double buffer (gmem prefetch)
    __shared__ __align__(16) float bias_sh[Gg];        // B: b_ih1 + b_hh1
    __shared__ __align__(16) float part_sh[800];       // half-row partials
    __shared__ __align__(16) float act_sh[Gg];         // A/C: activated gates
    __shared__ __align__(8) unsigned long long mb_full[RING];
    __shared__ __align__(8) unsigned long long mb_free[RING];

    const int role = blockIdx.x;  // 0=A, 1=B, 2=C
    const int tid = threadIdx.x;
    const bool iscomp = tid < 800;
    const int row = (tid < 400) ? tid : tid - 400;
    const int q = (tid < 400) ? 0 : 1;  // q0: elems 0..51 (13 f32x4), q1: 52..99 (12)
    const int nf4 = q ? 12 : 13;
    const int off = q ? 52 : 0;

    const float* W = (role == 0) ? Whh0 : (role == 1) ? Wih1 : Whh1;

    if (tid == 0) {
        for (int s = 0; s < RING; s++) {
            mbar_init1(smem_u32(&mb_full[s]));
            mbar_init1(smem_u32(&mb_free[s]));
        }
    }
    if (role != 1 && tid < Hh) h_sh[tid] = 0.f;
    if (role == 1 && tid < Gg) bias_sh[tid] = bih1[tid] + bhh1[tid];

    // remote base addresses (same smem layout in every CTA)
    uint32_t r_hring = 0, r_pring = 0, r_arr0 = 0, r_arr1 = 0;
    if (role == 0) {
        r_hring = mapa_u32(smem_u32(&hring[0][0]), 1);
        r_arr0 = mapa_u32(smem_u32(&mb_full[0]), 1);  // B.full
    } else if (role == 1) {
        r_pring = mapa_u32(smem_u32(&pring[0][0]), 2);
        r_arr0 = mapa_u32(smem_u32(&mb_full[0]), 2);  // C.full
        r_arr1 = mapa_u32(smem_u32(&mb_free[0]), 0);  // A.free
    } else {
        r_arr0 = mapa_u32(smem_u32(&mb_free[0]), 1);  // B.free
    }

    // weights in registers (<= 26 u64)
    unsigned long long wv[26];
    if (iscomp) {
        const ulonglong2* Wr = reinterpret_cast<const ulonglong2*>(W + row * Hh + off);
#pragma unroll
        for (int j = 0; j < 13; j++)
            if (j < nf4) { ulonglong2 v = Wr[j]; wv[2 * j] = v.x; wv[2 * j + 1] = v.y; }
    }

    float c = 0.f;
    cluster_sync_all();  // mbars initialized everywhere before any remote op

    // prologue: arrange iteration 0 inputs
    if (!iscomp) {
        int lane = tid - 800;
        if (role == 0) {
            const float4* s = reinterpret_cast<const float4*>(g_P);
            float4* d = reinterpret_cast<float4*>(pbuf[0]);
            d[lane] = s[lane]; d[lane + 32] = s[lane + 32]; d[lane + 64] = s[lane + 64];
            if (lane < 4) d[lane + 96] = s[lane + 96];
        } else if (lane == 0) {
            mbar_wait(smem_u32(&mb_full[0]), 0);  // B: h0[0] ready; C: P1[0] ready
        }
    }
    __syncthreads();

    for (int t = 0; t < Nn; t++) {
        const int slot = t & (RING - 1);

        // ---- phase 1: half-row dots | comm warp handles step t+1 inputs ----
        if (iscomp) {
            const float* din = (role == 1) ? hring[slot] : h_sh;
            const ulonglong2* h2 = reinterpret_cast<const ulonglong2*>(din + off);
            unsigned long long a0 = 0ull, a1 = 0ull;
#pragma unroll
            for (int j = 0; j < 13; j++)
                if (j < nf4) {
                    ulonglong2 hv = h2[j];  // LDS.128 broadcast
                    FMA2(a0, wv[2 * j], hv.x);
                    FMA2(a1, wv[2 * j + 1], hv.y);
                }
            part_sh[row * 2 + q] = unpack_sum(a0) + unpack_sum(a1);
        } else {
            int lane = tid - 800;
            int u = t + 1;
            if (u < Nn) {
                int us = u & (RING - 1), ue = u >> 2;
                if (role == 0) {
                    if (lane == 0 && u >= RING) mbar_wait(smem_u32(&mb_free[us]), (ue + 1) & 1);
                    const float4* s = reinterpret_cast<const float4*>(g_P + u * Gg);
                    float4* d = reinterpret_cast<float4*>(pbuf[u & 1]);
                    d[lane] = s[lane]; d[lane + 32] = s[lane + 32]; d[lane + 64] = s[lane + 64];
                    if (lane < 4) d[lane + 96] = s[lane + 96];
                } else if (role == 1) {
                    if (lane == 0) {
                        mbar_wait(smem_u32(&mb_full[us]), ue & 1);
                        if (u >= RING) mbar_wait(smem_u32(&mb_free[us]), (ue + 1) & 1);
                    }
                } else {
                    if (lane == 0) mbar_wait(smem_u32(&mb_full[us]), ue & 1);
                }
            }
        }
        __syncthreads();

        // ---- phase 2: combine halves; B ships P1 row to C; A/C activate gates ----
        if (tid < Gg) {
            float2 pp = reinterpret_cast<const float2*>(part_sh)[tid];
            if (role == 1) {
                st_remote(r_pring + (uint32_t)(slot * Gg + tid) * 4u, pp.x + pp.y + bias_sh[tid]);
            } else {
                float gv = pp.x + pp.y + ((role == 0) ? pbuf[t & 1][tid] : pring[slot][tid]);
                int gt = tid / 100;  // 0:i 1:f 2:g 3:o
                act_sh[tid] = (gt == 2) ? tanhap(gv) : fmaf(0.5f, tanhap(0.5f * gv), 0.5f);
            }
        }
        __syncthreads();

        // ---- phase 3: cell/hidden update (A ships h row to B; C stores h1) ----
        if (role != 1 && tid < Hh) {
            float si = act_sh[tid];
            float sf = act_sh[tid + 100];
            float tg = act_sh[tid + 200];
            float so = act_sh[tid + 300];
            c = fmaf(sf, c, si * tg);
            float hk = so * tanhap(c);
            h_sh[tid] = hk;
            if (role == 0) st_remote(r_hring + (uint32_t)(slot * Hh + tid) * 4u, hk);
            else g_H1[t * Hh + tid] = hk;
        }
        __syncthreads();

        // ---- post: posted arrives (cheap; barrier above orders the data stores) ----
        if (tid == 0) {
            if (role == 0) {
                mbar_arrive_remote(r_arr0 + slot * 8);                     // B.full[slot]
            } else if (role == 1) {
                mbar_arrive_remote(r_arr0 + slot * 8);                     // C.full[slot]
                mbar_arrive_remote(r_arr1 + slot * 8);                     // A.free[slot]
            } else {
                mbar_arrive_remote(r_arr0 + slot * 8);                     // B.free[slot]
            }
        }
    }
    cluster_sync_all();  // no CTA exits while peers may still touch its smem
}

// ---------------- K5a: fold scorer weights ----------------
__global__ void prep_u(const float* __restrict__ Wh2h, const float* __restrict__ bh2h,
                       const float* __restrict__ Wsc, const float* __restrict__ bsc) {
    int k = threadIdx.x;
    if (k < Hh) {
        float u1 = 0.f, u2 = 0.f;
        for (int m = 0; m < Hh; m++) {
            float s = Wsc[m];
            u1 = fmaf(Wh2h[m * 200 + k], s, u1);
            u2 = fmaf(Wh2h[m * 200 + 100 + k], s, u2);
        }
        g_u[k] = u1;
        g_u[100 + k] = u2;
    }
    if (k == 0) {
        float c0 = bsc[0];
        for (int m = 0; m < Hh; m++) c0 = fmaf(bh2h[m], Wsc[m], c0);
        g_u[200] = c0;
    }
}

// ---------------- K5b: EA/EB/S ----------------
__global__ __launch_bounds__(1024) void score_vec() {
    __shared__ float red[Nn];
    int i = threadIdx.x;
    const float* h = g_H1 + i * Hh;
    float sA = 0.f, sB = 0.f;
    for (int j = 0; j < Hh; j++) {
        float hv = h[j];
        sA = fmaf(hv, g_u[j], sA);
        sB = fmaf(hv, g_u[100 + j], sB);
    }
    float ea = __expf(sA);
    float eb = __expf(sB + g_u[200]);
    g_EA[i] = ea;
    g_EB[i] = eb;
    red[i] = ea;
    __syncthreads();
    for (int s = 512; s > 0; s >>= 1) {
        if (i < s) red[i] += red[i + s];
        __syncthreads();
    }
    if (i == 0) g_S = red[0];
}

// ---------------- K5c: scores ----------------
__global__ void fill_scores(float* __restrict__ out) {
    int i = blockIdx.x;
    float ea = g_EA[i];
    float S = g_S;
    for (int j = threadIdx.x; j < Nn; j += blockDim.x) {
        float eb = g_EB[j];
        out[i * Nn + j] = __fdividef(ea * eb, fmaf(S, eb, EPSV));
    }
}

// ---------------- K5d: labels ----------------
__global__ void fill_labels(const float* __restrict__ Wlab, const float* __restrict__ blab,
                            float* __restrict__ out) {
    __shared__ float hsh[Hh];
    __shared__ float esh[Ll];
    int r = blockIdx.x;  // 0..1022
    int tid = threadIdx.x;
    const float* h = g_H1 + (r + 1) * Hh;
    for (int j = tid; j < Hh; j += 64) hsh[j] = h[j];
    __syncthreads();
    if (tid < Ll) {
        float a = blab[tid];
        const float* wr = Wlab + tid * Hh;
        for (int j = 0; j < Hh; j++) a = fmaf(hsh[j], wr[j], a);
        esh[tid] = __expf(a);
    }
    __syncthreads();
    if (tid < Ll) {
        float s = 0.f;
        for (int j = 0; j < Ll; j++) s += esh[j];
        out[Nn * Nn + r * Ll + tid] = __fdividef(esh[tid], s + EPSV);
    }
}

// ---------------- launch ----------------
extern "C" void kernel_launch(void* const* d_in, const int* in_sizes, int n_in,
                              void* d_out, int out_size) {
    const int* wi = (const int*)d_in[0];
    const int* ti = (const int*)d_in[1];
    const float* wt = (const float*)d_in[2];
    const float* tt = (const float*)d_in[3];
    const float* Wih0 = (const float*)d_in[4];
    const float* Whh0 = (const float*)d_in[5];
    const float* bih0 = (const float*)d_in[6];
    const float* bhh0 = (const float*)d_in[7];
    const float* Wih1 = (const float*)d_in[8];
    const float* Whh1 = (const float*)d_in[9];
    const float* bih1 = (const float*)d_in[10];
    const float* bhh1 = (const float*)d_in[11];
    const float* Wh2h = (const float*)d_in[12];
    const float* bh2h = (const float*)d_in[13];
    const float* Wsc = (const float*)d_in[14];
    const float* bsc = (const float*)d_in[15];
    const float* Wlab = (const float*)d_in[16];
    const float* blab = (const float*)d_in[17];
    float* out = (float*)d_out;

    float *pE, *pP;
    cudaGetSymbolAddress((void**)&pE, g_E);
    cudaGetSymbolAddress((void**)&pP, g_P);

    dim3 gg(13, 16);

    gather_emb<<<Nn, 128>>>(wi, ti, wt, tt);
    gemm_bias<<<gg, 256>>>(pE, Wih0, bih0, bhh0, pP, KE);
    lstm_pipe<<<3, 832>>>(Whh0, Wih1, Whh1, bih1, bhh1);
    prep_u<<<1, 128>>>(Wh2h, bh2h, Wsc, bsc);
    score_vec<<<1, 1024>>>();
    fill_scores<<<Nn, 256>>>(out);
    fill_labels<<<Nn - 1, 64>>>(Wlab, blab, out);
}

// round 6
// speedup vs baseline: 1.2107x; 1.2107x over previous
#include <cuda_runtime.h>
#include <cstdint>

#define Nn 1024
#define Hh 100
#define Gg 400
#define KE 125
#define Ll 40
#define EPSV 1e-20f

// ---------------- scratch (device globals; no allocation allowed) ----------------
__device__ float g_E[Nn * KE];   // embeddings [1024,125]
__device__ float g_P[Nn * Gg];   // layer0 input projection (gemm output)
__device__ float g_P1[Nn * Gg];  // layer1 input projection (stage B output)
__device__ float g_H0[Nn * Hh];  // layer0 hidden states
__device__ float g_H1[Nn * Hh];  // layer1 hidden states
__device__ int g_flag0[Nn];      // h0[t] published
__device__ int g_flag1[Nn];      // P1[t] published
__device__ float g_EA[Nn];
__device__ float g_EB[Nn];
__device__ float g_S;

// ---------------- helpers ----------------
__device__ __forceinline__ float tanhap(float x) {
    float r;
    asm("tanh.approx.f32 %0, %1;" : "=f"(r) : "f"(x));
    return r;
}
#define FMA2(acc, a, b) asm("fma.rn.f32x2 %0, %1, %2, %0;" : "+l"(acc) : "l"(a), "l"(b))
__device__ __forceinline__ float unpack_sum(unsigned long long v) {
    float lo, hi;
    asm("mov.b64 {%0, %1}, %2;" : "=f"(lo), "=f"(hi) : "l"(v));
    return lo + hi;
}
__device__ __forceinline__ void spin_flag(const int* f) {
    int v;
    do { asm volatile("ld.acquire.gpu.b32 %0, [%1];" : "=r"(v) : "l"(f) : "memory"); } while (v == 0);
}
__device__ __forceinline__ void set_flag(int* f) {
    asm volatile("st.release.gpu.b32 [%0], %1;" :: "l"(f), "r"(1) : "memory");
}
__device__ __forceinline__ float4 ldg_cg4(const float4* p) {
    float4 v;
    asm volatile("ld.global.cg.v4.f32 {%0,%1,%2,%3}, [%4];"
                 : "=f"(v.x), "=f"(v.y), "=f"(v.z), "=f"(v.w) : "l"(p));
    return v;
}

// ---------------- K0: embedding gather ----------------
__global__ void gather_emb(const int* __restrict__ wi, const int* __restrict__ ti,
                           const float* __restrict__ wt, const float* __restrict__ tt) {
    int t = blockIdx.x;
    int w = wi[t];
    int g = ti[t];
    for (int j = threadIdx.x; j < KE; j += blockDim.x)
        g_E[t * KE + j] = (j < 100) ? wt[w * 100 + j] : tt[g * 25 + (j - 100)];
}

// ---------------- K0b: zero flags (every launch; flags persist across graph replays) ----------------
__global__ void zero_flags() {
    int i = threadIdx.x;
    g_flag0[i] = 0;
    g_flag1[i] = 0;
}

// ---------------- K1: P0 = E @ Wih0^T + b_ih0 + b_hh0 ----------------
__global__ __launch_bounds__(256) void gemm_bias(const float* __restrict__ X,
                                                 const float* __restrict__ W,
                                                 const float* __restrict__ b1,
                                                 const float* __restrict__ b2,
                                                 float* __restrict__ C, int K) {
    __shared__ float Xs[64 * 127];
    __shared__ float Ws[32 * 127];
    int m0 = blockIdx.y * 64;
    int n0 = blockIdx.x * 32;
    int tid = threadIdx.x;

    for (int idx = tid; idx < 64 * K; idx += 256) {
        int r = idx / K, c = idx - r * K;
        Xs[r * 127 + c] = X[(m0 + r) * K + c];
    }
    for (int idx = tid; idx < 32 * K; idx += 256) {
        int r = idx / K, c = idx - r * K;
        int n = n0 + r;
        Ws[r * 127 + c] = (n < Gg) ? W[n * K + c] : 0.f;
    }
    __syncthreads();

    int ty = tid >> 5, tx = tid & 31;
    float acc[8] = {0, 0, 0, 0, 0, 0, 0, 0};
    for (int k = 0; k < K; k++) {
        float wv = Ws[tx * 127 + k];
#pragma unroll
        for (int r = 0; r < 8; r++)
            acc[r] = fmaf(Xs[(ty + 8 * r) * 127 + k], wv, acc[r]);
    }
    int n = n0 + tx;
    if (n < Gg) {
        float bb = b1[n] + b2[n];
#pragma unroll
        for (int r = 0; r < 8; r++)
            C[(m0 + ty + 8 * r) * Gg + n] = acc[r] + bb;
    }
}

// ---------------- K2: 3-stage LSTM pipeline, gmem-flag handoff, 1 barrier/step ----------------
// grid=3 x 832 thr. role 0 (A): layer0 recurrence; role 1 (B): layer1 input proj;
// role 2 (C): layer1 recurrence. 800 compute threads: warp w (0..24), lane l:
//   unit u = w*4 + l/8, gate g = (l&7)/2, half hf = l&1, row r = g*100+u.
// Lane pair (2k,2k+1) = two halves of one row -> shfl-combine (no smem reduce).
// Owner lane (l%8==0) gathers f,g,o via 3 shfls, keeps c in-register, writes h.
// Comm warp (tid>=800): spin t+1 flag -> LDG -> STS -> PUBLISH t-1 (release drain
// overlapped with compute, the R4 killer fixed) -> barrier.
__global__ __launch_bounds__(832, 1) void lstm_pipe(const float* __restrict__ Whh0,
                                                    const float* __restrict__ Wih1,
                                                    const float* __restrict__ Whh1,
                                                    const float* __restrict__ bih1,
                                                    const float* __restrict__ bhh1) {
    __shared__ __align__(16) float h_sh[Hh];        // A/C recurrent state
    __shared__ __align__(16) float pbuf[2][Gg];     // A: P0 row, C: P1 row (double buffered)
    __shared__ __align__(16) float hbuf[2][Hh];     // B: h0 row (double buffered)

    const int role = blockIdx.x;
    const int tid = threadIdx.x;
    const bool iscomp = tid < 800;
    const int w = tid >> 5, l = tid & 31;
    const int u = w * 4 + (l >> 3);
    const int g = (l & 7) >> 1;
    const int hf = l & 1;
    const int r = g * 100 + u;
    const int nL = hf ? 12 : 13;       // ulonglong2 count: 52 + 48 elems
    const int off = hf * 52;

    const float* W = (role == 0) ? Whh0 : (role == 1) ? Wih1 : Whh1;

    // weights in registers (<= 26 u64 = 52 regs; R4-proven layout)
    unsigned long long wv[26];
    if (iscomp) {
        const ulonglong2* Wr = reinterpret_cast<const ulonglong2*>(W + r * Hh + off);
#pragma unroll
        for (int j = 0; j < 13; j++)
            if (j < nL) { ulonglong2 v = Wr[j]; wv[2 * j] = v.x; wv[2 * j + 1] = v.y; }
    }
    float bb = 0.f;
    if (role == 1 && iscomp && hf == 0) bb = bih1[r] + bhh1[r];
    float c = 0.f;
    if (role != 1 && tid < Hh) h_sh[tid] = 0.f;

    // prologue: stage inputs for t=0
    if (!iscomp) {
        int lane = tid - 800;
        if (role == 0) {
            const float4* s = reinterpret_cast<const float4*>(g_P);
            float4* d = reinterpret_cast<float4*>(pbuf[0]);
            for (int i = lane; i < 100; i += 32) d[i] = s[i];
        } else if (role == 1) {
            if (lane == 0) spin_flag(g_flag0);
            __syncwarp();
            const float4* s = reinterpret_cast<const float4*>(g_H0);
            float4* d = reinterpret_cast<float4*>(hbuf[0]);
            if (lane < 25) d[lane] = ldg_cg4(s + lane);
        } else {
            if (lane == 0) spin_flag(g_flag1);
            __syncwarp();
            const float4* s = reinterpret_cast<const float4*>(g_P1);
            float4* d = reinterpret_cast<float4*>(pbuf[0]);
            for (int i = lane; i < 100; i += 32) d[i] = ldg_cg4(s + i);
        }
    }
    __syncthreads();

    for (int t = 0; t < Nn; t++) {
        if (iscomp) {
            // half-row dot against h (own state for A/C, staged h0 for B)
            const float* hin = (role == 1) ? hbuf[t & 1] : h_sh;
            const ulonglong2* h2 = reinterpret_cast<const ulonglong2*>(hin + off);
            unsigned long long a0 = 0ull, a1 = 0ull;
#pragma unroll
            for (int j = 0; j < 13; j++)
                if (j < nL) {
                    ulonglong2 hv = h2[j];  // LDS.128 broadcast
                    FMA2(a0, wv[2 * j], hv.x);
                    FMA2(a1, wv[2 * j + 1], hv.y);
                }
            float a = unpack_sum(a0) + unpack_sum(a1);
            a += __shfl_down_sync(0xffffffffu, a, 1, 2);  // combine halves (even lanes valid)

            if (role == 1) {
                if (hf == 0) __stcg(&g_P1[t * Gg + r], a + bb);
            } else if (hf == 0) {
                float v = a + pbuf[t & 1][r];
                // gate nonlinearity: block 2 = tanh, others sigmoid via tanh
                float act = (g == 2) ? tanhap(v) : fmaf(0.5f, tanhap(0.5f * v), 0.5f);
                float vf = __shfl_sync(0x55555555u, act, 2, 8);
                float vg = __shfl_sync(0x55555555u, act, 4, 8);
                float vo = __shfl_sync(0x55555555u, act, 6, 8);
                if ((l & 7) == 0) {  // owner lane: own act = i gate
                    c = fmaf(vf, c, act * vg);
                    float hk = vo * tanhap(c);
                    h_sh[u] = hk;
                    if (role == 0) __stcg(&g_H0[t * Hh + u], hk);
                    else g_H1[t * Hh + u] = hk;
                }
            }
        } else {
            // comm warp, window t: fetch inputs for t+1, then publish t-1
            int lane = tid - 800;
            int nt = t + 1;
            if (role == 0) {
                if (nt < Nn) {
                    const float4* s = reinterpret_cast<const float4*>(g_P + nt * Gg);
                    float4* d = reinterpret_cast<float4*>(pbuf[nt & 1]);
                    for (int i = lane; i < 100; i += 32) d[i] = s[i];
                }
                if (t >= 1 && lane == 0) set_flag(g_flag0 + (t - 1));
            } else if (role == 1) {
                if (nt < Nn) {
                    if (lane == 0) spin_flag(g_flag0 + nt);
                    __syncwarp();
                    const float4* s = reinterpret_cast<const float4*>(g_H0 + nt * Hh);
                    float4* d = reinterpret_cast<float4*>(hbuf[nt & 1]);
                    if (lane < 25) d[lane] = ldg_cg4(s + lane);
                }
                if (t >= 1 && lane == 0) set_flag(g_flag1 + (t - 1));
            } else {
                if (nt < Nn) {
                    if (lane == 0) spin_flag(g_flag1 + nt);
                    __syncwarp();
                    const float4* s = reinterpret_cast<const float4*>(g_P1 + nt * Gg);
                    float4* d = reinterpret_cast<float4*>(pbuf[nt & 1]);
                    for (int i = lane; i < 100; i += 32) d[i] = ldg_cg4(s + i);
                }
            }
        }
        __syncthreads();
    }
    // final publishes (ordered after the last barrier)
    if (tid == 800) {
        if (role == 0) set_flag(g_flag0 + (Nn - 1));
        else if (role == 1) set_flag(g_flag1 + (Nn - 1));
    }
}

// ---------------- K5b: fold scorer weights + EA/EB/S (prep_u merged in) ----------------
__global__ __launch_bounds__(1024) void score_vec(const float* __restrict__ Wh2h,
                                                  const float* __restrict__ bh2h,
                                                  const float* __restrict__ Wsc,
                                                  const float* __restrict__ bsc) {
    __shared__ float u_sh[2 * Hh + 1];
    __shared__ float red[Nn];
    int i = threadIdx.x;

    if (i < 200) {
        int k = (i < 100) ? i : i - 100;
        int which = (i < 100) ? 0 : 1;
        const float* base = Wh2h + which * 100 + k;  // Wh2h[m*200 + which*100 + k]
        float s = 0.f;
        for (int m = 0; m < Hh; m++) s = fmaf(base[m * 200], Wsc[m], s);
        u_sh[which * 100 + k] = s;
    } else if (i == 200) {
        float c0 = bsc[0];
        for (int m = 0; m < Hh; m++) c0 = fmaf(bh2h[m], Wsc[m], c0);
        u_sh[200] = c0;
    }
    __syncthreads();

    const float* h = g_H1 + i * Hh;
    float sA = 0.f, sB = 0.f;
    for (int j = 0; j < Hh; j++) {
        float hv = h[j];
        sA = fmaf(hv, u_sh[j], sA);
        sB = fmaf(hv, u_sh[100 + j], sB);
    }
    float ea = __expf(sA);
    float eb = __expf(sB + u_sh[200]);
    g_EA[i] = ea;
    g_EB[i] = eb;
    red[i] = ea;
    __syncthreads();
    for (int s = 512; s > 0; s >>= 1) {
        if (i < s) red[i] += red[i + s];
        __syncthreads();
    }
    if (i == 0) g_S = red[0];
}

// ---------------- K5c: scores[i][j] = EA[i]*EB[j] / (S*EB[j] + eps) ----------------
__global__ void fill_scores(float* __restrict__ out) {
    int i = blockIdx.x;
    float ea = g_EA[i];
    float S = g_S;
    for (int j = threadIdx.x; j < Nn; j += blockDim.x) {
        float eb = g_EB[j];
        out[i * Nn + j] = __fdividef(ea * eb, fmaf(S, eb, EPSV));
    }
}

// ---------------- K5d: labels ----------------
__global__ void fill_labels(const float* __restrict__ Wlab, const float* __restrict__ blab,
                            float* __restrict__ out) {
    __shared__ float hsh[Hh];
    __shared__ float esh[Ll];
    int r = blockIdx.x;  // 0..1022
    int tid = threadIdx.x;
    const float* h = g_H1 + (r + 1) * Hh;
    for (int j = tid; j < Hh; j += 64) hsh[j] = h[j];
    __syncthreads();
    if (tid < Ll) {
        float a = blab[tid];
        const float* wr = Wlab + tid * Hh;
        for (int j = 0; j < Hh; j++) a = fmaf(hsh[j], wr[j], a);
        esh[tid] = __expf(a);
    }
    __syncthreads();
    if (tid < Ll) {
        float s = 0.f;
        for (int j = 0; j < Ll; j++) s += esh[j];
        out[Nn * Nn + r * Ll + tid] = __fdividef(esh[tid], s + EPSV);
    }
}

// ---------------- launch ----------------
extern "C" void kernel_launch(void* const* d_in, const int* in_sizes, int n_in,
                              void* d_out, int out_size) {
    const int* wi = (const int*)d_in[0];
    const int* ti = (const int*)d_in[1];
    const float* wt = (const float*)d_in[2];
    const float* tt = (const float*)d_in[3];
    const float* Wih0 = (const float*)d_in[4];
    const float* Whh0 = (const float*)d_in[5];
    const float* bih0 = (const float*)d_in[6];
    const float* bhh0 = (const float*)d_in[7];
    const float* Wih1 = (const float*)d_in[8];
    const float* Whh1 = (const float*)d_in[9];
    const float* bih1 = (const float*)d_in[10];
    const float* bhh1 = (const float*)d_in[11];
    const float* Wh2h = (const float*)d_in[12];
    const float* bh2h = (const float*)d_in[13];
    const float* Wsc = (const float*)d_in[14];
    const float* bsc = (const float*)d_in[15];
    const float* Wlab = (const float*)d_in[16];
    const float* blab = (const float*)d_in[17];
    float* out = (float*)d_out;

    float *pE, *pP;
    cudaGetSymbolAddress((void**)&pE, g_E);
    cudaGetSymbolAddress((void**)&pP, g_P);

    dim3 gg(13, 16);

    gather_emb<<<Nn, 128>>>(wi, ti, wt, tt);
    zero_flags<<<1, Nn>>>();
    gemm_bias<<<gg, 256>>>(pE, Wih0, bih0, bhh0, pP, KE);
    lstm_pipe<<<3, 832>>>(Whh0, Wih1, Whh1, bih1, bhh1);
    score_vec<<<1, 1024>>>(Wh2h, bh2h, Wsc, bsc);
    fill_scores<<<Nn, 256>>>(out);
    fill_labels<<<Nn - 1, 64>>>(Wlab, blab, out);
}

// round 7
// speedup vs baseline: 1.5025x; 1.2410x over previous
#include <cuda_runtime.h>
#include <cstdint>

#define Nn 1024
#define Hh 100
#define Gg 400
#define KE 125
#define Ll 40
#define EPSV 1e-20f

// ---------------- scratch (device globals; no allocation allowed) ----------------
__device__ float g_E[Nn * KE];   // embeddings [1024,125]
__device__ float g_P[Nn * Gg];   // layer0 input projection (gemm output)
__device__ float g_P1[Nn * Gg];  // layer1 input projection (stage B output)
__device__ float g_H0[Nn * Hh];  // layer0 hidden states
__device__ float g_H1[Nn * Hh];  // layer1 hidden states
__device__ int g_flag0[Nn];      // h0[t] published
__device__ int g_flag1[Nn];      // P1[t] published
__device__ float g_EA[Nn];
__device__ float g_EB[Nn];
__device__ float g_S;

// ---------------- helpers ----------------
__device__ __forceinline__ float tanhap(float x) {
    float r;
    asm("tanh.approx.f32 %0, %1;" : "=f"(r) : "f"(x));
    return r;
}
#define FMA2(acc, a, b) asm("fma.rn.f32x2 %0, %1, %2, %0;" : "+l"(acc) : "l"(a), "l"(b))
__device__ __forceinline__ float unpack_sum(unsigned long long v) {
    float lo, hi;
    asm("mov.b64 {%0, %1}, %2;" : "=f"(lo), "=f"(hi) : "l"(v));
    return lo + hi;
}
__device__ __forceinline__ void spin_flag(const int* f) {
    int v;
    do { asm volatile("ld.acquire.gpu.b32 %0, [%1];" : "=r"(v) : "l"(f) : "memory"); } while (v == 0);
}
__device__ __forceinline__ void set_flag(int* f) {
    asm volatile("st.release.gpu.b32 [%0], %1;" :: "l"(f), "r"(1) : "memory");
}
__device__ __forceinline__ float4 ldg_cg4(const float4* p) {
    float4 v;
    asm volatile("ld.global.cg.v4.f32 {%0,%1,%2,%3}, [%4];"
                 : "=f"(v.x), "=f"(v.y), "=f"(v.z), "=f"(v.w) : "l"(p));
    return v;
}
__device__ __forceinline__ float ldg_cg1(const float* p) {
    float v;
    asm volatile("ld.global.cg.f32 %0, [%1];" : "=f"(v) : "l"(p));
    return v;
}

// ---------------- K0: embedding gather ----------------
__global__ void gather_emb(const int* __restrict__ wi, const int* __restrict__ ti,
                           const float* __restrict__ wt, const float* __restrict__ tt) {
    int t = blockIdx.x;
    int w = wi[t];
    int g = ti[t];
    for (int j = threadIdx.x; j < KE; j += blockDim.x)
        g_E[t * KE + j] = (j < 100) ? wt[w * 100 + j] : tt[g * 25 + (j - 100)];
}

// ---------------- K0b: zero flags (every launch; flags persist across graph replays) ----------------
__global__ void zero_flags() {
    int i = threadIdx.x;
    g_flag0[i] = 0;
    g_flag1[i] = 0;
}

// ---------------- K1: P0 = E @ Wih0^T + b_ih0 + b_hh0 ----------------
__global__ __launch_bounds__(256) void gemm_bias(const float* __restrict__ X,
                                                 const float* __restrict__ W,
                                                 const float* __restrict__ b1,
                                                 const float* __restrict__ b2,
                                                 float* __restrict__ C, int K) {
    __shared__ float Xs[64 * 127];
    __shared__ float Ws[32 * 127];
    int m0 = blockIdx.y * 64;
    int n0 = blockIdx.x * 32;
    int tid = threadIdx.x;

    for (int idx = tid; idx < 64 * K; idx += 256) {
        int r = idx / K, c = idx - r * K;
        Xs[r * 127 + c] = X[(m0 + r) * K + c];
    }
    for (int idx = tid; idx < 32 * K; idx += 256) {
        int r = idx / K, c = idx - r * K;
        int n = n0 + r;
        Ws[r * 127 + c] = (n < Gg) ? W[n * K + c] : 0.f;
    }
    __syncthreads();

    int ty = tid >> 5, tx = tid & 31;
    float acc[8] = {0, 0, 0, 0, 0, 0, 0, 0};
    for (int k = 0; k < K; k++) {
        float wv = Ws[tx * 127 + k];
#pragma unroll
        for (int r = 0; r < 8; r++)
            acc[r] = fmaf(Xs[(ty + 8 * r) * 127 + k], wv, acc[r]);
    }
    int n = n0 + tx;
    if (n < Gg) {
        float bb = b1[n] + b2[n];
#pragma unroll
        for (int r = 0; r < 8; r++)
            C[(m0 + ty + 8 * r) * Gg + n] = acc[r] + bb;
    }
}

// ---------------- K2: 3-stage LSTM pipeline, minimal comm phase ----------------
// grid=3 x 832. role 0 (A): layer0 recurrence; 1 (B): layer1 input projection;
// 2 (C): layer1 recurrence. 800 compute threads: warp w(0..24), lane l:
//   unit u=w*4+l/8, gate g=(l&7)/2, half hf=l&1, row r=g*100+u.
// Additive rows (P0 for A, P1 for C) are PER-THREAD REGISTER prefetched one step
// ahead by hf0 lanes (latency hidden under the dot, no smem staging).
// Comm warp per step: lane0 publish(t-1) + spin(t+2) only; lanes 1..25 (B only)
// one float4 LDG+STS of h0[t+1]. h state double-buffered -> 1 barrier/step, no race.
__global__ __launch_bounds__(832, 1) void lstm_pipe(const float* __restrict__ Whh0,
                                                    const float* __restrict__ Wih1,
                                                    const float* __restrict__ Whh1,
                                                    const float* __restrict__ bih1,
                                                    const float* __restrict__ bhh1) {
    __shared__ __align__(16) float h_sh[2][Hh];   // A/C recurrent state (double buffered)
    __shared__ __align__(16) float hbuf[2][Hh];   // B: staged h0 rows (double buffered)

    const int role = blockIdx.x;
    const int tid = threadIdx.x;
    const bool iscomp = tid < 800;
    const int w = tid >> 5, l = tid & 31;
    const int u = w * 4 + (l >> 3);
    const int g = (l & 7) >> 1;
    const int hf = l & 1;
    const int r = g * 100 + u;
    const int nL = hf ? 12 : 13;  // ulonglong2 count: elems [0,52) | [52,100)
    const int off = hf * 52;

    const float* W = (role == 0) ? Whh0 : (role == 1) ? Wih1 : Whh1;
    const float* Pin = (role == 0) ? g_P : g_P1;

    // weights in registers (<= 26 u64 = 52 regs; proven spill-free at 72 regs total)
    unsigned long long wv[26];
    if (iscomp) {
        const ulonglong2* Wr = reinterpret_cast<const ulonglong2*>(W + r * Hh + off);
#pragma unroll
        for (int j = 0; j < 13; j++)
            if (j < nL) { ulonglong2 v = Wr[j]; wv[2 * j] = v.x; wv[2 * j + 1] = v.y; }
    }
    float bb = 0.f;
    if (role == 1 && iscomp && hf == 0) bb = bih1[r] + bhh1[r];
    float c = 0.f;
    if (role != 1 && tid < Hh) h_sh[0][tid] = 0.f;

    // ---- prologue: confirm flags for rows 0 and 1; B stages h0[0] ----
    if (!iscomp) {
        int lane = tid - 800;
        if (role == 1) {
            if (lane == 0) { spin_flag(g_flag0); spin_flag(g_flag0 + 1); }
            __syncwarp();
            if (lane >= 1 && lane <= 25)
                reinterpret_cast<float4*>(hbuf[0])[lane - 1] =
                    ldg_cg4(reinterpret_cast<const float4*>(g_H0) + (lane - 1));
        } else if (role == 2) {
            if (lane == 0) { spin_flag(g_flag1); spin_flag(g_flag1 + 1); }
        }
    }
    __syncthreads();

    // row-0 additive value (A: always ready; C: flag1[0] confirmed above)
    float p_cur = 0.f;
    if (iscomp && role != 1 && hf == 0) p_cur = ldg_cg1(Pin + r);

    for (int t = 0; t < Nn; t++) {
        if (iscomp) {
            // register prefetch of next additive row (flag for t+1 confirmed at step t-1)
            float p_nxt = 0.f;
            if (role != 1 && hf == 0 && t + 1 < Nn) p_nxt = ldg_cg1(Pin + (t + 1) * Gg + r);

            const float* hin = (role == 1) ? hbuf[t & 1] : h_sh[t & 1];
            const ulonglong2* h2 = reinterpret_cast<const ulonglong2*>(hin + off);
            unsigned long long a0 = 0ull, a1 = 0ull;
#pragma unroll
            for (int j = 0; j < 13; j++)
                if (j < nL) {
                    ulonglong2 hv = h2[j];  // LDS.128
                    FMA2(a0, wv[2 * j], hv.x);
                    FMA2(a1, wv[2 * j + 1], hv.y);
                }
            float a = unpack_sum(a0) + unpack_sum(a1);
            a += __shfl_down_sync(0xffffffffu, a, 1, 2);  // combine halves (even lanes)

            if (role == 1) {
                if (hf == 0) __stcg(&g_P1[t * Gg + r], a + bb);
            } else if (hf == 0) {
                float v = a + p_cur;
                float act = (g == 2) ? tanhap(v) : fmaf(0.5f, tanhap(0.5f * v), 0.5f);
                float vf = __shfl_sync(0x55555555u, act, 2, 8);
                float vg = __shfl_sync(0x55555555u, act, 4, 8);
                float vo = __shfl_sync(0x55555555u, act, 6, 8);
                if ((l & 7) == 0) {  // owner lane: own act = i gate
                    c = fmaf(vf, c, act * vg);
                    float hk = vo * tanhap(c);
                    h_sh[(t + 1) & 1][u] = hk;  // write NEXT buffer: no race with dot reads
                    if (role == 0) __stcg(&g_H0[t * Hh + u], hk);
                    else g_H1[t * Hh + u] = hk;
                }
            }
            p_cur = p_nxt;
        } else {
            int lane = tid - 800;
            if (role == 0) {
                if (lane == 0 && t >= 1) set_flag(g_flag0 + (t - 1));
            } else if (role == 1) {
                if (lane == 0 && t >= 1) set_flag(g_flag1 + (t - 1));
                if (lane >= 1 && lane <= 25 && t + 1 < Nn)
                    reinterpret_cast<float4*>(hbuf[(t + 1) & 1])[lane - 1] =
                        ldg_cg4(reinterpret_cast<const float4*>(g_H0 + (t + 1) * Hh) + (lane - 1));
                if (lane == 0 && t + 2 < Nn) spin_flag(g_flag0 + (t + 2));
            } else {
                if (lane == 0 && t + 2 < Nn) spin_flag(g_flag1 + (t + 2));
            }
        }
        __syncthreads();
    }
    // final publishes (ordered after the loop's last barrier)
    if (tid == 800) {
        if (role == 0) set_flag(g_flag0 + (Nn - 1));
        else if (role == 1) set_flag(g_flag1 + (Nn - 1));
    }
}

// ---------------- K5b: fold scorer weights + EA/EB/S ----------------
__global__ __launch_bounds__(1024) void score_vec(const float* __restrict__ Wh2h,
                                                  const float* __restrict__ bh2h,
                                                  const float* __restrict__ Wsc,
                                                  const float* __restrict__ bsc) {
    __shared__ float u_sh[2 * Hh + 1];
    __shared__ float red[Nn];
    int i = threadIdx.x;

    if (i < 200) {
        int k = (i < 100) ? i : i - 100;
        int which = (i < 100) ? 0 : 1;
        const float* base = Wh2h + which * 100 + k;
        float s = 0.f;
        for (int m = 0; m < Hh; m++) s = fmaf(base[m * 200], Wsc[m], s);
        u_sh[which * 100 + k] = s;
    } else if (i == 200) {
        float c0 = bsc[0];
        for (int m = 0; m < Hh; m++) c0 = fmaf(bh2h[m], Wsc[m], c0);
        u_sh[200] = c0;
    }
    __syncthreads();

    const float* h = g_H1 + i * Hh;
    float sA = 0.f, sB = 0.f;
    for (int j = 0; j < Hh; j++) {
        float hv = h[j];
        sA = fmaf(hv, u_sh[j], sA);
        sB = fmaf(hv, u_sh[100 + j], sB);
    }
    float ea = __expf(sA);
    float eb = __expf(sB + u_sh[200]);
    g_EA[i] = ea;
    g_EB[i] = eb;
    red[i] = ea;
    __syncthreads();
    for (int s = 512; s > 0; s >>= 1) {
        if (i < s) red[i] += red[i + s];
        __syncthreads();
    }
    if (i == 0) g_S = red[0];
}

// ---------------- K5c: scores[i][j] = EA[i]*EB[j] / (S*EB[j] + eps) ----------------
__global__ void fill_scores(float* __restrict__ out) {
    int i = blockIdx.x;
    float ea = g_EA[i];
    float S = g_S;
    for (int j = threadIdx.x; j < Nn; j += blockDim.x) {
        float eb = g_EB[j];
        out[i * Nn + j] = __fdividef(ea * eb, fmaf(S, eb, EPSV));
    }
}

// ---------------- K5d: labels ----------------
__global__ void fill_labels(const float* __restrict__ Wlab, const float* __restrict__ blab,
                            float* __restrict__ out) {
    __shared__ float hsh[Hh];
    __shared__ float esh[Ll];
    int r = blockIdx.x;  // 0..1022
    int tid = threadIdx.x;
    const float* h = g_H1 + (r + 1) * Hh;
    for (int j = tid; j < Hh; j += 64) hsh[j] = h[j];
    __syncthreads();
    if (tid < Ll) {
        float a = blab[tid];
        const float* wr = Wlab + tid * Hh;
        for (int j = 0; j < Hh; j++) a = fmaf(hsh[j], wr[j], a);
        esh[tid] = __expf(a);
    }
    __syncthreads();
    if (tid < Ll) {
        float s = 0.f;
        for (int j = 0; j < Ll; j++) s += esh[j];
        out[Nn * Nn + r * Ll + tid] = __fdividef(esh[tid], s + EPSV);
    }
}

// ---------------- launch ----------------
extern "C" void kernel_launch(void* const* d_in, const int* in_sizes, int n_in,
                              void* d_out, int out_size) {
    const int* wi = (const int*)d_in[0];
    const int* ti = (const int*)d_in[1];
    const float* wt = (const float*)d_in[2];
    const float* tt = (const float*)d_in[3];
    const float* Wih0 = (const float*)d_in[4];
    const float* Whh0 = (const float*)d_in[5];
    const float* bih0 = (const float*)d_in[6];
    const float* bhh0 = (const float*)d_in[7];
    const float* Wih1 = (const float*)d_in[8];
    const float* Whh1 = (const float*)d_in[9];
    const float* bih1 = (const float*)d_in[10];
    const float* bhh1 = (const float*)d_in[11];
    const float* Wh2h = (const float*)d_in[12];
    const float* bh2h = (const float*)d_in[13];
    const float* Wsc = (const float*)d_in[14];
    const float* bsc = (const float*)d_in[15];
    const float* Wlab = (const float*)d_in[16];
    const float* blab = (const float*)d_in[17];
    float* out = (float*)d_out;

    float *pE, *pP;
    cudaGetSymbolAddress((void**)&pE, g_E);
    cudaGetSymbolAddress((void**)&pP, g_P);

    dim3 gg(13, 16);

    gather_emb<<<Nn, 128>>>(wi, ti, wt, tt);
    zero_flags<<<1, Nn>>>();
    gemm_bias<<<gg, 256>>>(pE, Wih0, bih0, bhh0, pP, KE);
    lstm_pipe<<<3, 832>>>(Whh0, Wih1, Whh1, bih1, bhh1);
    score_vec<<<1, 1024>>>(Wh2h, bh2h, Wsc, bsc);
    fill_scores<<<Nn, 256>>>(out);
    fill_labels<<<Nn - 1, 64>>>(Wlab, blab, out);
}

// round 9
// speedup vs baseline: 1.8338x; 1.2205x over previous
#include <cuda_runtime.h>
#include <cstdint>

#define Nn 1024
#define Hh 100
#define Gg 400
#define KE 125
#define Ll 40
#define EPSV 1e-20f

// ---------------- scratch (device globals; no allocation allowed) ----------------
__device__ float g_E[Nn * KE];   // embeddings [1024,125]
__device__ float g_P[Nn * Gg];   // layer0 input projection (gemm output)
__device__ float g_P1[Nn * Gg];  // layer1 input projection (stage B output)
__device__ float g_H0[Nn * Hh];  // layer0 hidden states
__device__ float g_H1[Nn * Hh];  // layer1 hidden states
__device__ int g_cnt0;           // h0 rows < cnt0 published
__device__ int g_cnt1;           // P1 rows < cnt1 published
__device__ float g_EA[Nn];
__device__ float g_EB[Nn];
__device__ float g_S;

// ---------------- helpers ----------------
__device__ __forceinline__ float tanhap(float x) {
    float r;
    asm("tanh.approx.f32 %0, %1;" : "=f"(r) : "f"(x));
    return r;
}
#define FMA2(acc, a, b) asm("fma.rn.f32x2 %0, %1, %2, %0;" : "+l"(acc) : "l"(a), "l"(b))
__device__ __forceinline__ float unpack_sum(unsigned long long v) {
    float lo, hi;
    asm("mov.b64 {%0, %1}, %2;" : "=f"(lo), "=f"(hi) : "l"(v));
    return lo + hi;
}
__device__ __forceinline__ int ld_acq(const int* p) {
    int v;
    asm volatile("ld.acquire.gpu.b32 %0, [%1];" : "=r"(v) : "l"(p) : "memory");
    return v;
}
__device__ __forceinline__ void st_rel(int* p, int v) {
    asm volatile("st.release.gpu.b32 [%0], %1;" :: "l"(p), "r"(v) : "memory");
}
__device__ __forceinline__ float4 ldg_cg4(const float4* p) {
    float4 v;
    asm volatile("ld.global.cg.v4.f32 {%0,%1,%2,%3}, [%4];"
                 : "=f"(v.x), "=f"(v.y), "=f"(v.z), "=f"(v.w) : "l"(p));
    return v;
}
__device__ __forceinline__ float ldg_cg1(const float* p) {
    float v;
    asm volatile("ld.global.cg.f32 %0, [%1];" : "=f"(v) : "l"(p));
    return v;
}

// ---------------- K0: embedding gather ----------------
__global__ void gather_emb(const int* __restrict__ wi, const int* __restrict__ ti,
                           const float* __restrict__ wt, const float* __restrict__ tt) {
    int t = blockIdx.x;
    int w = wi[t];
    int g = ti[t];
    for (int j = threadIdx.x; j < KE; j += blockDim.x)
        g_E[t * KE + j] = (j < 100) ? wt[w * 100 + j] : tt[g * 25 + (j - 100)];
}

// ---------------- K0b: reset progress counters (every launch / graph replay) ----------------
__global__ void zero_cnt() {
    if (threadIdx.x == 0) { g_cnt0 = 0; g_cnt1 = 0; }
}

// ---------------- K1: P0 = E @ Wih0^T + b_ih0 + b_hh0 ----------------
__global__ __launch_bounds__(256) void gemm_bias(const float* __restrict__ X,
                                                 const float* __restrict__ W,
                                                 const float* __restrict__ b1,
                                                 const float* __restrict__ b2,
                                                 float* __restrict__ C, int K) {
    __shared__ float Xs[64 * 127];
    __shared__ float Ws[32 * 127];
    int m0 = blockIdx.y * 64;
    int n0 = blockIdx.x * 32;
    int tid = threadIdx.x;

    for (int idx = tid; idx < 64 * K; idx += 256) {
        int r = idx / K, c = idx - r * K;
        Xs[r * 127 + c] = X[(m0 + r) * K + c];
    }
    for (int idx = tid; idx < 32 * K; idx += 256) {
        int r = idx / K, c = idx - r * K;
        int n = n0 + r;
        Ws[r * 127 + c] = (n < Gg) ? W[n * K + c] : 0.f;
    }
    __syncthreads();

    int ty = tid >> 5, tx = tid & 31;
    float acc[8] = {0, 0, 0, 0, 0, 0, 0, 0};
    for (int k = 0; k < K; k++) {
        float wv = Ws[tx * 127 + k];
#pragma unroll
        for (int r = 0; r < 8; r++)
            acc[r] = fmaf(Xs[(ty + 8 * r) * 127 + k], wv, acc[r]);
    }
    int n = n0 + tx;
    if (n < Gg) {
        float bb = b1[n] + b2[n];
#pragma unroll
        for (int r = 0; r < 8; r++)
            C[(m0 + ty + 8 * r) * Gg + n] = acc[r] + bb;
    }
}

// ---------------- K2: 3-stage LSTM pipeline, batched-release handoff ----------------
// grid=3 x 832. role 0 (A): layer0 recurrence; 1 (B): layer1 input proj;
// 2 (C): layer1 recurrence. Compute threads (tid<800): warp w, lane l:
//   unit u=w*4+l/8, gate g=(l&7)/2, half hf=l&1, row r=g*100+u.
// Handoff via monotonic counters, ONE st.release per 8 steps (membar amortized);
// lane0 polls ld.acquire one step ahead; lanes 1..25 stage B's h0 row (the staging
// R8 accidentally deleted -- restored, this was R8's correctness bug).
// All row traffic coalesced: P rows prefetched by tid<400 (LDG+STS double buffer);
// B's P1 row staged in smem obuf, coalesced STG one step later.
__global__ __launch_bounds__(832, 1) void lstm_pipe(const float* __restrict__ Whh0,
                                                    const float* __restrict__ Wih1,
                                                    const float* __restrict__ Whh1,
                                                    const float* __restrict__ bih1,
                                                    const float* __restrict__ bhh1) {
    __shared__ __align__(16) float h_sh[2][Hh];   // A/C recurrent state (double buffered)
    __shared__ __align__(16) float hbuf[2][Hh];   // B: staged h0 rows
    __shared__ __align__(16) float pbuf[2][Gg];   // A/C: staged additive rows
    __shared__ __align__(16) float obuf[2][Gg];   // B: gate outputs awaiting writeback

    const int role = blockIdx.x;
    const int tid = threadIdx.x;
    const bool iscomp = tid < 800;
    const int w = tid >> 5, l = tid & 31;
    const int u = w * 4 + (l >> 3);
    const int g = (l & 7) >> 1;
    const int hf = l & 1;
    const int r = g * 100 + u;
    const int nL = hf ? 12 : 13;  // ulonglong2 count: elems [0,52) | [52,100)
    const int off = hf * 52;

    const float* W = (role == 0) ? Whh0 : (role == 1) ? Wih1 : Whh1;
    const float* Pin = (role == 0) ? g_P : g_P1;

    unsigned long long wv[26];
    if (iscomp) {
        const ulonglong2* Wr = reinterpret_cast<const ulonglong2*>(W + r * Hh + off);
#pragma unroll
        for (int j = 0; j < 13; j++)
            if (j < nL) { ulonglong2 v = Wr[j]; wv[2 * j] = v.x; wv[2 * j + 1] = v.y; }
    }
    float bb = 0.f;
    if (role == 1 && iscomp && hf == 0) bb = bih1[r] + bhh1[r];
    float c = 0.f;
    if (role != 1 && tid < Hh) h_sh[0][tid] = 0.f;

    int seen = 0;  // comm lane0's cached counter value

    // ---- prologue: establish rows {0,1} availability; B stages h0 row 0 ----
    if (!iscomp) {
        int lane = tid - 800;
        if (role == 1) {
            if (lane == 0) {
                while ((seen = ld_acq(&g_cnt0)) < 2) {}
            }
            __syncwarp();
            if (lane >= 1 && lane <= 25)
                reinterpret_cast<float4*>(hbuf[0])[lane - 1] =
                    ldg_cg4(reinterpret_cast<const float4*>(g_H0) + (lane - 1));
        } else if (role == 2) {
            if (lane == 0) {
                while ((seen = ld_acq(&g_cnt1)) < 2) {}
            }
        }
    }
    __syncthreads();
    if (role != 1 && tid < Gg) pbuf[0][tid] = ldg_cg1(Pin + tid);  // coalesced row 0
    __syncthreads();

    for (int t = 0; t < Nn; t++) {
        if (iscomp) {
            // B: coalesced writeback of last step's P1 row
            if (role == 1 && tid < Gg && t >= 1)
                __stcg(&g_P1[(t - 1) * Gg + tid], obuf[(t - 1) & 1][tid]);
            // A/C: coalesced prefetch of next additive row (availability confirmed
            // by lane0's spin at step t-1: seen >= t+2 covers row t+1)
            float pn = 0.f;
            const bool havep = (role != 1) && tid < Gg && (t + 1 < Nn);
            if (havep) pn = ldg_cg1(Pin + (t + 1) * Gg + tid);

            const float* hin = (role == 1) ? hbuf[t & 1] : h_sh[t & 1];
            const ulonglong2* h2 = reinterpret_cast<const ulonglong2*>(hin + off);
            unsigned long long a0 = 0ull, a1 = 0ull;
#pragma unroll
            for (int j = 0; j < 13; j++)
                if (j < nL) {
                    ulonglong2 hv = h2[j];  // LDS.128
                    FMA2(a0, wv[2 * j], hv.x);
                    FMA2(a1, wv[2 * j + 1], hv.y);
                }
            float a = unpack_sum(a0) + unpack_sum(a1);
            a += __shfl_down_sync(0xffffffffu, a, 1, 2);  // combine halves (even lanes)

            if (role == 1) {
                if (hf == 0) obuf[t & 1][r] = a + bb;  // STS; coalesced STG next step
            } else if (hf == 0) {
                float v = a + pbuf[t & 1][r];
                float act = (g == 2) ? tanhap(v) : fmaf(0.5f, tanhap(0.5f * v), 0.5f);
                float vf = __shfl_sync(0x55555555u, act, 2, 8);
                float vg = __shfl_sync(0x55555555u, act, 4, 8);
                float vo = __shfl_sync(0x55555555u, act, 6, 8);
                if ((l & 7) == 0) {  // owner lane: own act = i gate
                    c = fmaf(vf, c, act * vg);
                    float hk = vo * tanhap(c);
                    h_sh[(t + 1) & 1][u] = hk;  // next buffer: no race with dot readers
                    if (role == 0) __stcg(&g_H0[t * Hh + u], hk);
                    else g_H1[t * Hh + u] = hk;
                }
            }
            if (havep) pbuf[(t + 1) & 1][tid] = pn;  // STS after dot: LDG latency hidden
        } else {
            int lane = tid - 800;
            if (role == 0) {
                if (lane == 0 && (t & 7) == 0 && t > 0) st_rel(&g_cnt0, t);  // rows < t
            } else if (role == 1) {
                if (lane == 0) {
                    if ((t & 7) == 0 && t > 0) st_rel(&g_cnt1, t - 1);  // rows < t-1
                    if (t + 2 < Nn && seen < t + 3) {
                        while ((seen = ld_acq(&g_cnt0)) < t + 3) {}
                    }
                }
                // stage h0[t+1] (guarded by lane0's spin at step t-1: seen >= t+2)
                if (lane >= 1 && lane <= 25 && t + 1 < Nn)
                    reinterpret_cast<float4*>(hbuf[(t + 1) & 1])[lane - 1] =
                        ldg_cg4(reinterpret_cast<const float4*>(g_H0 + (t + 1) * Hh) + (lane - 1));
            } else {
                if (lane == 0 && t + 2 < Nn && seen < t + 3) {
                    while ((seen = ld_acq(&g_cnt1)) < t + 3) {}
                }
            }
        }
        __syncthreads();
    }
    // epilogue: B writes back its final row; final releases
    if (role == 1 && tid < Gg)
        __stcg(&g_P1[(Nn - 1) * Gg + tid], obuf[(Nn - 1) & 1][tid]);
    __syncthreads();
    if (tid == 800) {
        if (role == 0) st_rel(&g_cnt0, Nn);
        else if (role == 1) st_rel(&g_cnt1, Nn);
    }
}

// ---------------- K5b: fold scorer weights + EA/EB/S ----------------
__global__ __launch_bounds__(1024) void score_vec(const float* __restrict__ Wh2h,
                                                  const float* __restrict__ bh2h,
                                                  const float* __restrict__ Wsc,
                                                  const float* __restrict__ bsc) {
    __shared__ float u_sh[2 * Hh + 1];
    __shared__ float red[Nn];
    int i = threadIdx.x;

    if (i < 200) {
        int k = (i < 100) ? i : i - 100;
        int which = (i < 100) ? 0 : 1;
        const float* base = Wh2h + which * 100 + k;
        float s = 0.f;
        for (int m = 0; m < Hh; m++) s = fmaf(base[m * 200], Wsc[m], s);
        u_sh[which * 100 + k] = s;
    } else if (i == 200) {
        float c0 = bsc[0];
        for (int m = 0; m < Hh; m++) c0 = fmaf(bh2h[m], Wsc[m], c0);
        u_sh[200] = c0;
    }
    __syncthreads();

    const float* h = g_H1 + i * Hh;
    float sA = 0.f, sB = 0.f;
    for (int j = 0; j < Hh; j++) {
        float hv = h[j];
        sA = fmaf(hv, u_sh[j], sA);
        sB = fmaf(hv, u_sh[100 + j], sB);
    }
    float ea = __expf(sA);
    float eb = __expf(sB + u_sh[200]);
    g_EA[i] = ea;
    g_EB[i] = eb;
    red[i] = ea;
    __syncthreads();
    for (int s = 512; s > 0; s >>= 1) {
        if (i < s) red[i] += red[i + s];
        __syncthreads();
    }
    if (i == 0) g_S = red[0];
}

// ---------------- K5c: scores[i][j] = EA[i]*EB[j] / (S*EB[j] + eps) ----------------
__global__ void fill_scores(float* __restrict__ out) {
    int i = blockIdx.x;
    float ea = g_EA[i];
    float S = g_S;
    for (int j = threadIdx.x; j < Nn; j += blockDim.x) {
        float eb = g_EB[j];
        out[i * Nn + j] = __fdividef(ea * eb, fmaf(S, eb, EPSV));
    }
}

// ---------------- K5d: labels ----------------
__global__ void fill_labels(const float* __restrict__ Wlab, const float* __restrict__ blab,
                            float* __restrict__ out) {
    __shared__ float hsh[Hh];
    __shared__ float esh[Ll];
    int r = blockIdx.x;  // 0..1022
    int tid = threadIdx.x;
    const float* h = g_H1 + (r + 1) * Hh;
    for (int j = tid; j < Hh; j += 64) hsh[j] = h[j];
    __syncthreads();
    if (tid < Ll) {
        float a = blab[tid];
        const float* wr = Wlab + tid * Hh;
        for (int j = 0; j < Hh; j++) a = fmaf(hsh[j], wr[j], a);
        esh[tid] = __expf(a);
    }
    __syncthreads();
    if (tid < Ll) {
        float s = 0.f;
        for (int j = 0; j < Ll; j++) s += esh[j];
        out[Nn * Nn + r * Ll + tid] = __fdividef(esh[tid], s + EPSV);
    }
}

// ---------------- launch ----------------
extern "C" void kernel_launch(void* const* d_in, const int* in_sizes, int n_in,
                              void* d_out, int out_size) {
    const int* wi = (const int*)d_in[0];
    const int* ti = (const int*)d_in[1];
    const float* wt = (const float*)d_in[2];
    const float* tt = (const float*)d_in[3];
    const float* Wih0 = (const float*)d_in[4];
    const float* Whh0 = (const float*)d_in[5];
    const float* bih0 = (const float*)d_in[6];
    const float* bhh0 = (const float*)d_in[7];
    const float* Wih1 = (const float*)d_in[8];
    const float* Whh1 = (const float*)d_in[9];
    const float* bih1 = (const float*)d_in[10];
    const float* bhh1 = (const float*)d_in[11];
    const float* Wh2h = (const float*)d_in[12];
    const float* bh2h = (const float*)d_in[13];
    const float* Wsc = (const float*)d_in[14];
    const float* bsc = (const float*)d_in[15];
    const float* Wlab = (const float*)d_in[16];
    const float* blab = (const float*)d_in[17];
    float* out = (float*)d_out;

    float *pE, *pP;
    cudaGetSymbolAddress((void**)&pE, g_E);
    cudaGetSymbolAddress((void**)&pP, g_P);

    dim3 gg(13, 16);

    gather_emb<<<Nn, 128>>>(wi, ti, wt, tt);
    zero_cnt<<<1, 32>>>();
    gemm_bias<<<gg, 256>>>(pE, Wih0, bih0, bhh0, pP, KE);
    lstm_pipe<<<3, 832>>>(Whh0, Wih1, Whh1, bih1, bhh1);
    score_vec<<<1, 1024>>>(Wh2h, bh2h, Wsc, bsc);
    fill_scores<<<Nn, 256>>>(out);
    fill_labels<<<Nn - 1, 64>>>(Wlab, blab, out);
}

// round 10
// speedup vs baseline: 2.0530x; 1.1195x over previous
#include <cuda_runtime.h>
#include <cstdint>

#define Nn 1024
#define Hh 100
#define Gg 400
#define KE 125
#define Ll 40
#define EPSV 1e-20f

// ---------------- scratch (device globals; no allocation allowed) ----------------
__device__ float g_E[Nn * KE];   // embeddings [1024,125]
__device__ float g_P[Nn * Gg];   // layer0 input projection (gemm output)
__device__ float g_P1[Nn * Gg];  // layer1 input projection (stage B output)
__device__ float g_H0[Nn * Hh];  // layer0 hidden states
__device__ float g_H1[Nn * Hh];  // layer1 hidden states
__device__ int g_cnt0;           // h0 rows < cnt0 published
__device__ int g_cnt1;           // P1 rows < cnt1 published
__device__ float g_EA[Nn];
__device__ float g_EB[Nn];
__device__ float g_S;

// ---------------- helpers ----------------
__device__ __forceinline__ float tanhap(float x) {
    float r;
    asm("tanh.approx.f32 %0, %1;" : "=f"(r) : "f"(x));
    return r;
}
#define FMA2(acc, a, b) asm("fma.rn.f32x2 %0, %1, %2, %0;" : "+l"(acc) : "l"(a), "l"(b))
__device__ __forceinline__ float unpack_sum(unsigned long long v) {
    float lo, hi;
    asm("mov.b64 {%0, %1}, %2;" : "=f"(lo), "=f"(hi) : "l"(v));
    return lo + hi;
}
__device__ __forceinline__ int ld_acq(const int* p) {
    int v;
    asm volatile("ld.acquire.gpu.b32 %0, [%1];" : "=r"(v) : "l"(p) : "memory");
    return v;
}
__device__ __forceinline__ void st_rel(int* p, int v) {
    asm volatile("st.release.gpu.b32 [%0], %1;" :: "l"(p), "r"(v) : "memory");
}
__device__ __forceinline__ float4 ldg_cg4(const float4* p) {
    float4 v;
    asm volatile("ld.global.cg.v4.f32 {%0,%1,%2,%3}, [%4];"
                 : "=f"(v.x), "=f"(v.y), "=f"(v.z), "=f"(v.w) : "l"(p));
    return v;
}
__device__ __forceinline__ float ldg_cg1(const float* p) {
    float v;
    asm volatile("ld.global.cg.f32 %0, [%1];" : "=f"(v) : "l"(p));
    return v;
}

// ---------------- K0: embedding gather ----------------
__global__ void gather_emb(const int* __restrict__ wi, const int* __restrict__ ti,
                           const float* __restrict__ wt, const float* __restrict__ tt) {
    int t = blockIdx.x;
    int w = wi[t];
    int g = ti[t];
    for (int j = threadIdx.x; j < KE; j += blockDim.x)
        g_E[t * KE + j] = (j < 100) ? wt[w * 100 + j] : tt[g * 25 + (j - 100)];
}

// ---------------- K0b: reset progress counters (every launch / graph replay) ----------------
__global__ void zero_cnt() {
    if (threadIdx.x == 0) { g_cnt0 = 0; g_cnt1 = 0; }
}

// ---------------- K1: P0 = E @ Wih0^T + b_ih0 + b_hh0 ----------------
__global__ __launch_bounds__(256) void gemm_bias(const float* __restrict__ X,
                                                 const float* __restrict__ W,
                                                 const float* __restrict__ b1,
                                                 const float* __restrict__ b2,
                                                 float* __restrict__ C, int K) {
    __shared__ float Xs[64 * 127];
    __shared__ float Ws[32 * 127];
    int m0 = blockIdx.y * 64;
    int n0 = blockIdx.x * 32;
    int tid = threadIdx.x;

    for (int idx = tid; idx < 64 * K; idx += 256) {
        int r = idx / K, c = idx - r * K;
        Xs[r * 127 + c] = X[(m0 + r) * K + c];
    }
    for (int idx = tid; idx < 32 * K; idx += 256) {
        int r = idx / K, c = idx - r * K;
        int n = n0 + r;
        Ws[r * 127 + c] = (n < Gg) ? W[n * K + c] : 0.f;
    }
    __syncthreads();

    int ty = tid >> 5, tx = tid & 31;
    float acc[8] = {0, 0, 0, 0, 0, 0, 0, 0};
    for (int k = 0; k < K; k++) {
        float wv = Ws[tx * 127 + k];
#pragma unroll
        for (int r = 0; r < 8; r++)
            acc[r] = fmaf(Xs[(ty + 8 * r) * 127 + k], wv, acc[r]);
    }
    int n = n0 + tx;
    if (n < Gg) {
        float bb = b1[n] + b2[n];
#pragma unroll
        for (int r = 0; r < 8; r++)
            C[(m0 + ty + 8 * r) * Gg + n] = acc[r] + bb;
    }
}

// ---------------- K2: 3-stage LSTM pipeline, 1-thread/row gate-group geometry ----------------
// grid=3 x 448 (13 compute warps + 1 comm warp). role 0 (A): layer0 recurrence;
// 1 (B): layer1 input proj; 2 (C): layer1 recurrence.
// Compute thread tid<400: unit u=tid>>2, gate g=tid&3, row r=g*100+u.
// All 4 gates of a unit in one 4-lane group -> h update via 3 width-4 shfls,
// 1 barrier/step. Each thread holds its full weight row: 50 u64 regs
// (cap 65536/448=146; est ~135, no spill).
// Handoff: monotonic counters, 1 st.release per 8 steps, lookahead spin (R9-proven).
__global__ __launch_bounds__(448, 1) void lstm_pipe(const float* __restrict__ Whh0,
                                                    const float* __restrict__ Wih1,
                                                    const float* __restrict__ Whh1,
                                                    const float* __restrict__ bih1,
                                                    const float* __restrict__ bhh1) {
    __shared__ __align__(16) float h_sh[2][Hh];   // A/C recurrent state (double buffered)
    __shared__ __align__(16) float hbuf[2][Hh];   // B: staged h0 rows
    __shared__ __align__(16) float pbuf[2][Gg];   // A/C: staged additive rows
    __shared__ __align__(16) float obuf[2][Gg];   // B: gate outputs awaiting writeback

    const int role = blockIdx.x;
    const int tid = threadIdx.x;
    const bool iscomp = tid < 400;
    const int u = tid >> 2;      // unit 0..99
    const int g = tid & 3;       // gate 0:i 1:f 2:g 3:o
    const int r = g * 100 + u;   // weight row
    // warp 12 has only lanes 0-15 in compute: shfl mask must cover exactly those
    const unsigned shmask = (tid < 384) ? 0xffffffffu : 0x0000ffffu;

    const float* W = (role == 0) ? Whh0 : (role == 1) ? Wih1 : Whh1;
    const float* Pin = (role == 0) ? g_P : g_P1;

    // full weight row in registers: 25 ulonglong2 = 50 u64 regs
    unsigned long long wv[50];
    if (iscomp) {
        const ulonglong2* Wr = reinterpret_cast<const ulonglong2*>(W + r * Hh);
#pragma unroll
        for (int j = 0; j < 25; j++) {
            ulonglong2 v = Wr[j];
            wv[2 * j] = v.x;
            wv[2 * j + 1] = v.y;
        }
    }
    float bb = 0.f;
    if (role == 1 && iscomp) bb = bih1[r] + bhh1[r];
    float c = 0.f;
    if (role != 1 && tid < Hh) h_sh[0][tid] = 0.f;

    int seen = 0;  // comm lane0's cached counter value

    // ---- prologue: rows {0,1} availability; B stages h0 row 0 ----
    if (!iscomp && tid >= 416) {
        int lane = tid - 416;
        if (role == 1) {
            if (lane == 0) {
                while ((seen = ld_acq(&g_cnt0)) < 2) {}
            }
            __syncwarp();
            if (lane < 25)
                reinterpret_cast<float4*>(hbuf[0])[lane] =
                    ldg_cg4(reinterpret_cast<const float4*>(g_H0) + lane);
        } else if (role == 2) {
            if (lane == 0) {
                while ((seen = ld_acq(&g_cnt1)) < 2) {}
            }
        }
    }
    __syncthreads();
    if (role != 1 && iscomp) pbuf[0][tid] = ldg_cg1(Pin + tid);  // coalesced row 0
    __syncthreads();

    for (int t = 0; t < Nn; t++) {
        if (iscomp) {
            // B: coalesced writeback of last step's P1 row
            if (role == 1 && t >= 1)
                __stcg(&g_P1[(t - 1) * Gg + tid], obuf[(t - 1) & 1][tid]);
            // A/C: coalesced prefetch of next additive row (availability confirmed
            // by comm lane0's spin at step t-1)
            float pn = 0.f;
            const bool havep = (role != 1) && (t + 1 < Nn);
            if (havep) pn = ldg_cg1(Pin + (t + 1) * Gg + tid);

            const float* hin = (role == 1) ? hbuf[t & 1] : h_sh[t & 1];
            const ulonglong2* h2 = reinterpret_cast<const ulonglong2*>(hin);
            unsigned long long a0 = 0ull, a1 = 0ull, a2 = 0ull, a3 = 0ull;
#pragma unroll
            for (int j = 0; j < 25; j++) {
                ulonglong2 hv = h2[j];  // LDS.128 broadcast (all lanes same addr)
                if (j & 1) {
                    FMA2(a2, wv[2 * j], hv.x);
                    FMA2(a3, wv[2 * j + 1], hv.y);
                } else {
                    FMA2(a0, wv[2 * j], hv.x);
                    FMA2(a1, wv[2 * j + 1], hv.y);
                }
            }
            float a = (unpack_sum(a0) + unpack_sum(a1)) + (unpack_sum(a2) + unpack_sum(a3));

            if (role == 1) {
                obuf[t & 1][r] = a + bb;  // STS; coalesced STG next step
            } else {
                float v = a + pbuf[t & 1][r];
                float act = (g == 2) ? tanhap(v) : fmaf(0.5f, tanhap(0.5f * v), 0.5f);
                // gate exchange within the 4-lane unit group
                float vf = __shfl_sync(shmask, act, 1, 4);
                float vg = __shfl_sync(shmask, act, 2, 4);
                float vo = __shfl_sync(shmask, act, 3, 4);
                if (g == 0) {  // owner lane: own act = i gate
                    c = fmaf(vf, c, act * vg);
                    float hk = vo * tanhap(c);
                    h_sh[(t + 1) & 1][u] = hk;  // next buffer: no race with dot readers
                    if (role == 0) __stcg(&g_H0[t * Hh + u], hk);
                    else g_H1[t * Hh + u] = hk;
                }
            }
            if (havep) pbuf[(t + 1) & 1][tid] = pn;  // STS after dot: LDG latency hidden
        } else if (tid >= 416) {
            int lane = tid - 416;
            if (role == 0) {
                if (lane == 0 && (t & 7) == 0 && t > 0) st_rel(&g_cnt0, t);  // rows < t
            } else if (role == 1) {
                if (lane == 0) {
                    if ((t & 7) == 0 && t > 0) st_rel(&g_cnt1, t - 1);  // rows < t-1
                    if (t + 2 < Nn && seen < t + 3) {
                        while ((seen = ld_acq(&g_cnt0)) < t + 3) {}
                    }
                }
                // stage h0[t+1] (guarded by lane0's spin at step t-1: seen >= t+2)
                if (lane < 25 && t + 1 < Nn)
                    reinterpret_cast<float4*>(hbuf[(t + 1) & 1])[lane] =
                        ldg_cg4(reinterpret_cast<const float4*>(g_H0 + (t + 1) * Hh) + lane);
            } else {
                if (lane == 0 && t + 2 < Nn && seen < t + 3) {
                    while ((seen = ld_acq(&g_cnt1)) < t + 3) {}
                }
            }
        }
        __syncthreads();
    }
    // epilogue: B writes back its final row; final releases
    if (role == 1 && iscomp)
        __stcg(&g_P1[(Nn - 1) * Gg + tid], obuf[(Nn - 1) & 1][tid]);
    __syncthreads();
    if (tid == 416) {
        if (role == 0) st_rel(&g_cnt0, Nn);
        else if (role == 1) st_rel(&g_cnt1, Nn);
    }
}

// ---------------- K5b: fold scorer weights + EA/EB/S ----------------
__global__ __launch_bounds__(1024) void score_vec(const float* __restrict__ Wh2h,
                                                  const float* __restrict__ bh2h,
                                                  const float* __restrict__ Wsc,
                                                  const float* __restrict__ bsc) {
    __shared__ float u_sh[2 * Hh + 1];
    __shared__ float red[Nn];
    int i = threadIdx.x;

    if (i < 200) {
        int k = (i < 100) ? i : i - 100;
        int which = (i < 100) ? 0 : 1;
        const float* base = Wh2h + which * 100 + k;
        float s = 0.f;
        for (int m = 0; m < Hh; m++) s = fmaf(base[m * 200], Wsc[m], s);
        u_sh[which * 100 + k] = s;
    } else if (i == 200) {
        float c0 = bsc[0];
        for (int m = 0; m < Hh; m++) c0 = fmaf(bh2h[m], Wsc[m], c0);
        u_sh[200] = c0;
    }
    __syncthreads();

    const float* h = g_H1 + i * Hh;
    float sA = 0.f, sB = 0.f;
    for (int j = 0; j < Hh; j++) {
        float hv = h[j];
        sA = fmaf(hv, u_sh[j], sA);
        sB = fmaf(hv, u_sh[100 + j], sB);
    }
    float ea = __expf(sA);
    float eb = __expf(sB + u_sh[200]);
    g_EA[i] = ea;
    g_EB[i] = eb;
    red[i] = ea;
    __syncthreads();
    for (int s = 512; s > 0; s >>= 1) {
        if (i < s) red[i] += red[i + s];
        __syncthreads();
    }
    if (i == 0) g_S = red[0];
}

// ---------------- K5c: scores[i][j] = EA[i]*EB[j] / (S*EB[j] + eps) ----------------
__global__ void fill_scores(float* __restrict__ out) {
    int i = blockIdx.x;
    float ea = g_EA[i];
    float S = g_S;
    for (int j = threadIdx.x; j < Nn; j += blockDim.x) {
        float eb = g_EB[j];
        out[i * Nn + j] = __fdividef(ea * eb, fmaf(S, eb, EPSV));
    }
}

// ---------------- K5d: labels ----------------
__global__ void fill_labels(const float* __restrict__ Wlab, const float* __restrict__ blab,
                            float* __restrict__ out) {
    __shared__ float hsh[Hh];
    __shared__ float esh[Ll];
    int r = blockIdx.x;  // 0..1022
    int tid = threadIdx.x;
    const float* h = g_H1 + (r + 1) * Hh;
    for (int j = tid; j < Hh; j += 64) hsh[j] = h[j];
    __syncthreads();
    if (tid < Ll) {
        float a = blab[tid];
        const float* wr = Wlab + tid * Hh;
        for (int j = 0; j < Hh; j++) a = fmaf(hsh[j], wr[j], a);
        esh[tid] = __expf(a);
    }
    __syncthreads();
    if (tid < Ll) {
        float s = 0.f;
        for (int j = 0; j < Ll; j++) s += esh[j];
        out[Nn * Nn + r * Ll + tid] = __fdividef(esh[tid], s + EPSV);
    }
}

// ---------------- launch ----------------
extern "C" void kernel_launch(void* const* d_in, const int* in_sizes, int n_in,
                              void* d_out, int out_size) {
    const int* wi = (const int*)d_in[0];
    const int* ti = (const int*)d_in[1];
    const float* wt = (const float*)d_in[2];
    const float* tt = (const float*)d_in[3];
    const float* Wih0 = (const float*)d_in[4];
    const float* Whh0 = (const float*)d_in[5];
    const float* bih0 = (const float*)d_in[6];
    const float* bhh0 = (const float*)d_in[7];
    const float* Wih1 = (const float*)d_in[8];
    const float* Whh1 = (const float*)d_in[9];
    const float* bih1 = (const float*)d_in[10];
    const float* bhh1 = (const float*)d_in[11];
    const float* Wh2h = (const float*)d_in[12];
    const float* bh2h = (const float*)d_in[13];
    const float* Wsc = (const float*)d_in[14];
    const float* bsc = (const float*)d_in[15];
    const float* Wlab = (const float*)d_in[16];
    const float* blab = (const float*)d_in[17];
    float* out = (float*)d_out;

    float *pE, *pP;
    cudaGetSymbolAddress((void**)&pE, g_E);
    cudaGetSymbolAddress((void**)&pP, g_P);

    dim3 gg(13, 16);

    gather_emb<<<Nn, 128>>>(wi, ti, wt, tt);
    zero_cnt<<<1, 32>>>();
    gemm_bias<<<gg, 256>>>(pE, Wih0, bih0, bhh0, pP, KE);
    lstm_pipe<<<3, 448>>>(Whh0, Wih1, Whh1, bih1, bhh1);
    score_vec<<<1, 1024>>>(Wh2h, bh2h, Wsc, bsc);
    fill_scores<<<Nn, 256>>>(out);
    fill_labels<<<Nn - 1, 64>>>(Wlab, blab, out);
}